// round 11
// baseline (speedup 1.0000x reference)
#include <cuda_runtime.h>
#include <cuda_fp16.h>
#include <math.h>

#define NN   100000
#define EE   1600000
#define TOTE 1700000   // E + N self loops
#define FIN  128
#define FHID 64
#define FOUT 40
#define KSTEPS 10
#define ALPHA 0.1f
#define CSR_BLOCKS 98

// ---------------- scratch (static device globals; no allocation) ----------------
__device__ int   g_cnt[NN];
__device__ int   g_rowptr[NN + 1];
__device__ int   g_pos[NN];
__device__ float g_dinv[NN];
__device__ int   g_esrc[TOTE];           // src index only (weights folded into iterate)
__device__ int   g_agg[CSR_BLOCKS];      // scan block aggregates (0 = not ready)
__device__ int   g_barcnt;
__device__ int   g_bargen;
// half-precision node-feature buffers, 128B per row (both layers use 128B row stride)
__device__ uint4 g_h0[NN * 8];           // teleport target
__device__ uint4 g_bufA[NN * 8];
__device__ uint4 g_bufB[NN * 8];

// ---------------- software grid barrier (all CSR_BLOCKS resident) ----------------
__device__ __forceinline__ void sw_barrier() {
    __syncthreads();
    if (threadIdx.x == 0) {
        __threadfence();
        int gen = *(volatile int*)&g_bargen;
        int t = atomicAdd(&g_barcnt, 1);
        if (t == CSR_BLOCKS - 1) {
            g_barcnt = 0;
            __threadfence();
            *(volatile int*)&g_bargen = gen + 1;
        } else {
            while (*(volatile int*)&g_bargen == gen) {}
        }
        __threadfence();
    }
    __syncthreads();
}

// ---------------- fused CSR build: degree -> scan -> fill ----------------
__global__ void __launch_bounds__(1024) k_csr(const int* __restrict__ src,
                                              const int* __restrict__ dst) {
    __shared__ int sh[1024];
    __shared__ int s_off;
    int t = threadIdx.x, b = blockIdx.x;
    int gid = b * 1024 + t;
    const int NT = CSR_BLOCKS * 1024;

    // phase A: in-degree histogram (g_cnt zeroed by k_gemm1)
    for (int e = gid; e < EE; e += NT)
        atomicAdd(&g_cnt[dst[e]], 1);
    sw_barrier();

    // phase B: exclusive scan of (deg+1) across all nodes, plus dinv
    int v = (gid < NN) ? (g_cnt[gid] + 1) : 0;   // +1 self loop
    if (gid < NN) g_dinv[gid] = rsqrtf((float)v);
    sh[t] = v;
    __syncthreads();
    for (int off = 1; off < 1024; off <<= 1) {
        int add = (t >= off) ? sh[t - off] : 0;
        __syncthreads();
        sh[t] += add;
        __syncthreads();
    }
    int incl = sh[t];
    if (t == 1023) *(volatile int*)&g_agg[b] = sh[1023];   // block total (>0 always)
    if (t < 32) {
        int sum = 0;
        for (int p = t; p < b; p += 32) {
            int a;
            do { a = *(volatile int*)&g_agg[p]; } while (a == 0);
            sum += a;
        }
#pragma unroll
        for (int off = 16; off > 0; off >>= 1)
            sum += __shfl_xor_sync(0xFFFFFFFFu, sum, off);
        if (t == 0) s_off = sum;
    }
    __syncthreads();
    int rp = s_off + incl - v;
    if (gid < NN) { g_rowptr[gid] = rp; g_pos[gid] = rp; }
    if (gid == 0) g_rowptr[NN] = TOTE;
    sw_barrier();

    // phase C: counting-sort fill (src-only records)
    for (int e = gid; e < TOTE; e += NT) {
        int s, d;
        if (e < EE) { s = src[e]; d = dst[e]; }
        else        { s = d = e - EE; }
        int p = atomicAdd(&g_pos[d], 1);
        g_esrc[p] = s;
    }
}

// ---------------- GEMM1: h0 = relu(x@W1+b1) (half); also zeroes CSR state ----------------
__global__ void __launch_bounds__(256) k_gemm1(const float* __restrict__ x,
                                               const float* __restrict__ W1,
                                               const float* __restrict__ b1) {
    // zero CSR-build state (runs before k_csr in stream order)
    {
        int tg = blockIdx.x * 256 + threadIdx.x;
        if (tg < NN) g_cnt[tg] = 0;
        if (tg < CSR_BLOCKS) g_agg[tg] = 0;
        if (tg == 0) { g_barcnt = 0; g_bargen = 0; }
    }
    __shared__ float Ws[FIN * FHID];
    __shared__ float bs[FHID];
    int tid = threadIdx.x;
    for (int i = tid; i < FIN * FHID / 4; i += 256)
        ((float4*)Ws)[i] = ((const float4*)W1)[i];
    if (tid < FHID) bs[tid] = b1[tid];
    __syncthreads();

    int cg = tid & 7;          // owns cols [cg*8, cg*8+8)
    int rsub = tid >> 3;       // 0..31
    int rowBase = blockIdx.x * 128;

    float acc[4][8];
#pragma unroll
    for (int i = 0; i < 4; i++)
#pragma unroll
        for (int j = 0; j < 8; j++) acc[i][j] = 0.f;

    for (int k4 = 0; k4 < FIN / 4; k4++) {
        float4 xv[4];
#pragma unroll
        for (int i = 0; i < 4; i++) {
            int rr = rowBase + rsub + 32 * i;
            xv[i] = (rr < NN) ? __ldg((const float4*)(x + (size_t)rr * FIN) + k4)
                              : make_float4(0.f, 0.f, 0.f, 0.f);
        }
#pragma unroll
        for (int kk = 0; kk < 4; kk++) {
            int k = k4 * 4 + kk;
            float4 w0 = *(const float4*)&Ws[k * FHID + cg * 8];
            float4 w1 = *(const float4*)&Ws[k * FHID + cg * 8 + 4];
            float wv[8] = {w0.x, w0.y, w0.z, w0.w, w1.x, w1.y, w1.z, w1.w};
#pragma unroll
            for (int i = 0; i < 4; i++) {
                float xs = (kk == 0) ? xv[i].x : (kk == 1) ? xv[i].y
                          : (kk == 2) ? xv[i].z : xv[i].w;
#pragma unroll
                for (int j = 0; j < 8; j++) acc[i][j] += xs * wv[j];
            }
        }
    }
#pragma unroll
    for (int i = 0; i < 4; i++) {
        int rr = rowBase + rsub + 32 * i;
        if (rr < NN) {
            float r[8];
#pragma unroll
            for (int j = 0; j < 8; j++) r[j] = fmaxf(acc[i][j] + bs[cg * 8 + j], 0.f);
            uint4 oh;
            *(__half2*)&oh.x = __floats2half2_rn(r[0], r[1]);
            *(__half2*)&oh.y = __floats2half2_rn(r[2], r[3]);
            *(__half2*)&oh.z = __floats2half2_rn(r[4], r[5]);
            *(__half2*)&oh.w = __floats2half2_rn(r[6], r[7]);
            g_h0[(size_t)rr * 8 + cg] = oh;
        }
    }
}

// ---------------- GEMM2: h0_40 = relu(x10@W2+b2) (half, 128B row stride) ----------------
__global__ void __launch_bounds__(256) k_gemm2(const __half* __restrict__ xin,
                                               const float* __restrict__ W2,
                                               const float* __restrict__ b2,
                                               __half* __restrict__ h0o) {
    __shared__ float Ws[FHID * FOUT];
    __shared__ float bs[FOUT];
    int tid = threadIdx.x;
    for (int i = tid; i < FHID * FOUT; i += 256) Ws[i] = W2[i];
    if (tid < FOUT) bs[tid] = b2[tid];
    __syncthreads();

    int cg = tid & 7;          // cols cg + 8*j, j<5
    int rsub = tid >> 3;
    int rowBase = blockIdx.x * 128;

    float acc[4][5];
#pragma unroll
    for (int i = 0; i < 4; i++)
#pragma unroll
        for (int j = 0; j < 5; j++) acc[i][j] = 0.f;

    for (int k8 = 0; k8 < FHID / 8; k8++) {
        float xf[4][8];
#pragma unroll
        for (int i = 0; i < 4; i++) {
            int rr = rowBase + rsub + 32 * i;
            uint4 v = (rr < NN) ? __ldg((const uint4*)xin + (size_t)rr * 8 + k8)
                                : make_uint4(0u, 0u, 0u, 0u);
            float2 f0 = __half22float2(*(__half2*)&v.x);
            float2 f1 = __half22float2(*(__half2*)&v.y);
            float2 f2 = __half22float2(*(__half2*)&v.z);
            float2 f3 = __half22float2(*(__half2*)&v.w);
            xf[i][0] = f0.x; xf[i][1] = f0.y; xf[i][2] = f1.x; xf[i][3] = f1.y;
            xf[i][4] = f2.x; xf[i][5] = f2.y; xf[i][6] = f3.x; xf[i][7] = f3.y;
        }
#pragma unroll
        for (int kk = 0; kk < 8; kk++) {
            int k = k8 * 8 + kk;
            float wv[5];
#pragma unroll
            for (int j = 0; j < 5; j++) wv[j] = Ws[k * FOUT + cg + 8 * j];
#pragma unroll
            for (int i = 0; i < 4; i++)
#pragma unroll
                for (int j = 0; j < 5; j++) acc[i][j] += xf[i][kk] * wv[j];
        }
    }
#pragma unroll
    for (int i = 0; i < 4; i++) {
        int rr = rowBase + rsub + 32 * i;
        if (rr < NN) {
#pragma unroll
            for (int j = 0; j < 5; j++) {
                int c = cg + 8 * j;
                float v = fmaxf(acc[i][j] + bs[c], 0.f);
                h0o[(size_t)rr * 64 + c] = __float2half_rn(v);   // 128B stride
            }
        }
    }
}

// helpers
__device__ __forceinline__ __half2 u2h(unsigned u) { return *(__half2*)&u; }
__device__ __forceinline__ unsigned h2u(__half2 h) { return *(unsigned*)&h; }
__device__ __forceinline__ void accH(__half2 (&a)[4], uint4 v) {
    a[0] = __hadd2(a[0], u2h(v.x));
    a[1] = __hadd2(a[1], u2h(v.y));
    a[2] = __hadd2(a[2], u2h(v.z));
    a[3] = __hadd2(a[3], u2h(v.w));
}
__device__ __forceinline__ void accF(float (&fa)[8], uint4 v, float w) {
    float2 f0 = __half22float2(u2h(v.x));
    float2 f1 = __half22float2(u2h(v.y));
    float2 f2 = __half22float2(u2h(v.z));
    float2 f3 = __half22float2(u2h(v.w));
    fa[0] = fmaf(w, f0.x, fa[0]); fa[1] = fmaf(w, f0.y, fa[1]);
    fa[2] = fmaf(w, f1.x, fa[2]); fa[3] = fmaf(w, f1.y, fa[3]);
    fa[4] = fmaf(w, f2.x, fa[4]); fa[5] = fmaf(w, f2.y, fa[5]);
    fa[6] = fmaf(w, f3.x, fa[6]); fa[7] = fmaf(w, f3.y, fa[7]);
}

// ---------------- prop F=64: warp/node, 4 groups x 8 lanes x uint4 (4 edges/LDG) --------
template <bool FIRST, bool FINAL>
__global__ void __launch_bounds__(256) k_prop64(const uint4* __restrict__ zin,
                                                const uint4* __restrict__ h0,
                                                uint4* __restrict__ zout) {
    int gw = (blockIdx.x * blockDim.x + threadIdx.x) >> 5;
    int lane = threadIdx.x & 31;
    if (gw >= NN) return;
    int beg = __ldg(&g_rowptr[gw]);
    int end = __ldg(&g_rowptr[gw + 1]);
    int grp = lane >> 3;      // 0..3, edge stride 4
    int sub = lane & 7;       // uint4 slot within 128B row
    __half2 hz = __floats2half2_rn(0.f, 0.f);
    __half2 a0[4] = {hz, hz, hz, hz}, a1[4] = {hz, hz, hz, hz};
    float fa[8] = {0.f, 0.f, 0.f, 0.f, 0.f, 0.f, 0.f, 0.f};
    int j = beg + grp;
    for (; j + 4 < end; j += 8) {
        int s0 = __ldg(&g_esrc[j]);
        int s1 = __ldg(&g_esrc[j + 4]);
        uint4 v0 = __ldg(zin + (size_t)s0 * 8 + sub);
        uint4 v1 = __ldg(zin + (size_t)s1 * 8 + sub);
        if (FIRST) {
            accF(fa, v0, __ldg(&g_dinv[s0]));
            accF(fa, v1, __ldg(&g_dinv[s1]));
        } else {
            accH(a0, v0);
            accH(a1, v1);
        }
    }
    if (j < end) {
        int s0 = __ldg(&g_esrc[j]);
        uint4 v0 = __ldg(zin + (size_t)s0 * 8 + sub);
        if (FIRST) accF(fa, v0, __ldg(&g_dinv[s0]));
        else       accH(a0, v0);
    }
    unsigned r[4];
    if (FIRST) {
        r[0] = h2u(__floats2half2_rn(fa[0], fa[1]));
        r[1] = h2u(__floats2half2_rn(fa[2], fa[3]));
        r[2] = h2u(__floats2half2_rn(fa[4], fa[5]));
        r[3] = h2u(__floats2half2_rn(fa[6], fa[7]));
    } else {
#pragma unroll
        for (int k = 0; k < 4; k++) r[k] = h2u(__hadd2(a0[k], a1[k]));
    }
#pragma unroll
    for (int k = 0; k < 4; k++) {
        unsigned t = __shfl_down_sync(0xFFFFFFFFu, r[k], 16);
        r[k] = h2u(__hadd2(u2h(r[k]), u2h(t)));
        t = __shfl_down_sync(0xFFFFFFFFu, r[k], 8);
        r[k] = h2u(__hadd2(u2h(r[k]), u2h(t)));
    }
    if (grp == 0) {           // lanes 0..7 hold the full reduced row slice
        float dv = __ldg(&g_dinv[gw]);
        uint4 hv = __ldg(h0 + (size_t)gw * 8 + sub);
        float2 s0 = __half22float2(u2h(r[0]));
        float2 s1 = __half22float2(u2h(r[1]));
        float2 s2 = __half22float2(u2h(r[2]));
        float2 s3 = __half22float2(u2h(r[3]));
        float2 t0 = __half22float2(u2h(hv.x));
        float2 t1 = __half22float2(u2h(hv.y));
        float2 t2 = __half22float2(u2h(hv.z));
        float2 t3 = __half22float2(u2h(hv.w));
        float c = (1.0f - ALPHA) * dv;
        float sc = FINAL ? 1.0f : dv;
        uint4 o;
        *(__half2*)&o.x = __floats2half2_rn(sc * (c * s0.x + ALPHA * t0.x),
                                            sc * (c * s0.y + ALPHA * t0.y));
        *(__half2*)&o.y = __floats2half2_rn(sc * (c * s1.x + ALPHA * t1.x),
                                            sc * (c * s1.y + ALPHA * t1.y));
        *(__half2*)&o.z = __floats2half2_rn(sc * (c * s2.x + ALPHA * t2.x),
                                            sc * (c * s2.y + ALPHA * t2.y));
        *(__half2*)&o.w = __floats2half2_rn(sc * (c * s3.x + ALPHA * t3.x),
                                            sc * (c * s3.y + ALPHA * t3.y));
        zout[(size_t)gw * 8 + sub] = o;
    }
}

// ---------------- prop F=40: warp/node, 6 groups x 5 lanes x uint4 (6 edges/LDG) --------
// rows padded to 128B stride (8 uint4, first 5 used)
template <bool FIRST>
__device__ __forceinline__ void prop40_acc(int gw, int lane, int grp, int sub,
                                           const uint4* __restrict__ zin,
                                           unsigned (&r)[4]) {
    int beg = __ldg(&g_rowptr[gw]);
    int end = __ldg(&g_rowptr[gw + 1]);
    __half2 hz = __floats2half2_rn(0.f, 0.f);
    __half2 a0[4] = {hz, hz, hz, hz}, a1[4] = {hz, hz, hz, hz};
    float fa[8] = {0.f, 0.f, 0.f, 0.f, 0.f, 0.f, 0.f, 0.f};
    int j = (grp < 6) ? beg + grp : end;
    for (; j + 6 < end; j += 12) {
        int s0 = __ldg(&g_esrc[j]);
        int s1 = __ldg(&g_esrc[j + 6]);
        uint4 v0 = __ldg(zin + (size_t)s0 * 8 + sub);
        uint4 v1 = __ldg(zin + (size_t)s1 * 8 + sub);
        if (FIRST) {
            accF(fa, v0, __ldg(&g_dinv[s0]));
            accF(fa, v1, __ldg(&g_dinv[s1]));
        } else {
            accH(a0, v0);
            accH(a1, v1);
        }
    }
    if (j < end) {
        int s0 = __ldg(&g_esrc[j]);
        uint4 v0 = __ldg(zin + (size_t)s0 * 8 + sub);
        if (FIRST) accF(fa, v0, __ldg(&g_dinv[s0]));
        else       accH(a0, v0);
    }
    if (FIRST) {
        r[0] = h2u(__floats2half2_rn(fa[0], fa[1]));
        r[1] = h2u(__floats2half2_rn(fa[2], fa[3]));
        r[2] = h2u(__floats2half2_rn(fa[4], fa[5]));
        r[3] = h2u(__floats2half2_rn(fa[6], fa[7]));
    } else {
#pragma unroll
        for (int k = 0; k < 4; k++) r[k] = h2u(__hadd2(a0[k], a1[k]));
    }
    // reduce 6 groups (lanes 5g+sub) onto group 0: +15, then +5 and +10
#pragma unroll
    for (int k = 0; k < 4; k++) {
        unsigned t = __shfl_down_sync(0xFFFFFFFFu, r[k], 15);
        unsigned b = h2u(__hadd2(u2h(r[k]), u2h(t)));
        unsigned t5  = __shfl_down_sync(0xFFFFFFFFu, b, 5);
        unsigned t10 = __shfl_down_sync(0xFFFFFFFFu, b, 10);
        r[k] = h2u(__hadd2(__hadd2(u2h(b), u2h(t5)), u2h(t10)));
    }
}

template <bool FIRST>
__global__ void __launch_bounds__(256) k_prop40(const uint4* __restrict__ zin,
                                                const uint4* __restrict__ h0,
                                                uint4* __restrict__ zout) {
    int gw = (blockIdx.x * blockDim.x + threadIdx.x) >> 5;
    int lane = threadIdx.x & 31;
    if (gw >= NN) return;
    int grp = lane / 5;
    int sub = lane - grp * 5;
    unsigned r[4];
    prop40_acc<FIRST>(gw, lane, grp, sub, zin, r);
    if (grp == 0) {           // lanes 0..4
        float dv = __ldg(&g_dinv[gw]);
        uint4 hv = __ldg(h0 + (size_t)gw * 8 + sub);
        float2 s0 = __half22float2(u2h(r[0]));
        float2 s1 = __half22float2(u2h(r[1]));
        float2 s2 = __half22float2(u2h(r[2]));
        float2 s3 = __half22float2(u2h(r[3]));
        float2 t0 = __half22float2(u2h(hv.x));
        float2 t1 = __half22float2(u2h(hv.y));
        float2 t2 = __half22float2(u2h(hv.z));
        float2 t3 = __half22float2(u2h(hv.w));
        float c = (1.0f - ALPHA) * dv;
        uint4 o;
        *(__half2*)&o.x = __floats2half2_rn(dv * (c * s0.x + ALPHA * t0.x),
                                            dv * (c * s0.y + ALPHA * t0.y));
        *(__half2*)&o.y = __floats2half2_rn(dv * (c * s1.x + ALPHA * t1.x),
                                            dv * (c * s1.y + ALPHA * t1.y));
        *(__half2*)&o.z = __floats2half2_rn(dv * (c * s2.x + ALPHA * t2.x),
                                            dv * (c * s2.y + ALPHA * t2.y));
        *(__half2*)&o.w = __floats2half2_rn(dv * (c * s3.x + ALPHA * t3.x),
                                            dv * (c * s3.y + ALPHA * t3.y));
        zout[(size_t)gw * 8 + sub] = o;
    }
}

// final F=40 step fused with log_softmax, fp32 output
__global__ void __launch_bounds__(256) k_prop40_lsm(const uint4* __restrict__ zin,
                                                    const uint4* __restrict__ h0,
                                                    float* __restrict__ out) {
    int gw = (blockIdx.x * blockDim.x + threadIdx.x) >> 5;
    int lane = threadIdx.x & 31;
    if (gw >= NN) return;
    int grp = lane / 5;
    int sub = lane - grp * 5;
    unsigned r[4];
    prop40_acc<false>(gw, lane, grp, sub, zin, r);
    bool act = (grp == 0);
    float v[8];
    if (act) {
        float dv = __ldg(&g_dinv[gw]);
        uint4 hv = __ldg(h0 + (size_t)gw * 8 + sub);
        float2 s0 = __half22float2(u2h(r[0]));
        float2 s1 = __half22float2(u2h(r[1]));
        float2 s2 = __half22float2(u2h(r[2]));
        float2 s3 = __half22float2(u2h(r[3]));
        float2 t0 = __half22float2(u2h(hv.x));
        float2 t1 = __half22float2(u2h(hv.y));
        float2 t2 = __half22float2(u2h(hv.z));
        float2 t3 = __half22float2(u2h(hv.w));
        float c = (1.0f - ALPHA) * dv;
        v[0] = c * s0.x + ALPHA * t0.x;  v[1] = c * s0.y + ALPHA * t0.y;
        v[2] = c * s1.x + ALPHA * t1.x;  v[3] = c * s1.y + ALPHA * t1.y;
        v[4] = c * s2.x + ALPHA * t2.x;  v[5] = c * s2.y + ALPHA * t2.y;
        v[6] = c * s3.x + ALPHA * t3.x;  v[7] = c * s3.y + ALPHA * t3.y;
    }
    float m = -INFINITY;
    if (act) {
#pragma unroll
        for (int i = 0; i < 8; i++) m = fmaxf(m, v[i]);
    }
#pragma unroll
    for (int off = 16; off > 0; off >>= 1)
        m = fmaxf(m, __shfl_xor_sync(0xFFFFFFFFu, m, off));
    float s = 0.f;
    if (act) {
#pragma unroll
        for (int i = 0; i < 8; i++) s += expf(v[i] - m);
    }
#pragma unroll
    for (int off = 16; off > 0; off >>= 1)
        s += __shfl_xor_sync(0xFFFFFFFFu, s, off);
    float lg = m + logf(s);
    if (act) {
        float4 o0 = make_float4(v[0] - lg, v[1] - lg, v[2] - lg, v[3] - lg);
        float4 o1 = make_float4(v[4] - lg, v[5] - lg, v[6] - lg, v[7] - lg);
        float* p = out + (size_t)gw * FOUT + sub * 8;
        *(float4*)p = o0;
        *(float4*)(p + 4) = o1;
    }
}

// ---------------- launch ----------------
extern "C" void kernel_launch(void* const* d_in, const int* in_sizes, int n_in,
                              void* d_out, int out_size) {
    const float* x    = (const float*)d_in[0];
    const int*   edge = (const int*)d_in[1];
    const float* W1   = (const float*)d_in[2];
    const float* b1   = (const float*)d_in[3];
    const float* W2   = (const float*)d_in[4];
    const float* b2   = (const float*)d_in[5];
    const int* src = edge;
    const int* dst = edge + EE;

    uint4 *h0, *A, *B;
    cudaGetSymbolAddress((void**)&h0, g_h0);
    cudaGetSymbolAddress((void**)&A, g_bufA);
    cudaGetSymbolAddress((void**)&B, g_bufB);

    const int PROP_BLOCKS = (NN * 32 + 255) / 256;

    // 1: GEMM1 (graph-independent) + zero CSR state
    k_gemm1<<<(NN + 127) / 128, 256>>>(x, W1, b1);
    // 2: fused CSR build
    k_csr<<<CSR_BLOCKS, 1024>>>(src, dst);

    // layer 1 propagation (10 steps); #3 = FIRST, #4 = steady (profiled)
    k_prop64<true, false><<<PROP_BLOCKS, 256>>>(h0, h0, A);
    const uint4* cur = A;
    uint4* nxt = B;
    for (int it = 0; it < KSTEPS - 2; it++) {
        k_prop64<false, false><<<PROP_BLOCKS, 256>>>(cur, h0, nxt);
        const uint4* t = nxt; nxt = (uint4*)cur; cur = t;
    }
    k_prop64<false, true><<<PROP_BLOCKS, 256>>>(cur, h0, nxt);   // unscaled x10

    // layer 2 (all F=40 rows use 128B stride)
    uint4* x10 = nxt;
    uint4* other = (x10 == A) ? B : A;
    k_gemm2<<<(NN + 127) / 128, 256>>>((const __half*)x10, W2, b2, (__half*)h0);
    k_prop40<true><<<PROP_BLOCKS, 256>>>(h0, h0, other);
    cur = other;
    nxt = x10;
    for (int it = 0; it < KSTEPS - 2; it++) {
        k_prop40<false><<<PROP_BLOCKS, 256>>>(cur, h0, nxt);
        const uint4* t = nxt; nxt = (uint4*)cur; cur = t;
    }
    k_prop40_lsm<<<PROP_BLOCKS, 256>>>(cur, h0, (float*)d_out);
}

// round 12
// speedup vs baseline: 1.1138x; 1.1138x over previous
#include <cuda_runtime.h>
#include <cuda_fp16.h>
#include <math.h>

#define NN   100000
#define EE   1600000
#define TOTE 1700000   // E + N self loops
#define FIN  128
#define FHID 64
#define FOUT 40
#define KSTEPS 10
#define ALPHA 0.1f
#define CSR_BLOCKS 98

// ---------------- scratch (static device globals; no allocation) ----------------
__device__ int   g_cnt[NN];
__device__ int   g_rowptr[NN + 1];
__device__ int   g_pos[NN];
__device__ float g_dinv[NN];
__device__ int   g_esrc[TOTE];           // src index only (weights folded into iterate)
__device__ int   g_agg[CSR_BLOCKS];      // scan block aggregates (0 = not ready)
__device__ int   g_barcnt;
__device__ int   g_bargen;
// half-precision node-feature buffers, 128B per row (max F=64 halves)
__device__ uint4 g_h0[NN * 8];           // teleport target
__device__ uint4 g_bufA[NN * 8];
__device__ uint4 g_bufB[NN * 8];

// ---------------- software grid barrier (all CSR_BLOCKS resident) ----------------
__device__ __forceinline__ void sw_barrier() {
    __syncthreads();
    if (threadIdx.x == 0) {
        __threadfence();
        int gen = *(volatile int*)&g_bargen;
        int t = atomicAdd(&g_barcnt, 1);
        if (t == CSR_BLOCKS - 1) {
            g_barcnt = 0;
            __threadfence();
            *(volatile int*)&g_bargen = gen + 1;
        } else {
            while (*(volatile int*)&g_bargen == gen) {}
        }
        __threadfence();
    }
    __syncthreads();
}

// ---------------- fused CSR build: degree -> scan -> fill ----------------
__global__ void __launch_bounds__(1024) k_csr(const int* __restrict__ src,
                                              const int* __restrict__ dst) {
    __shared__ int sh[1024];
    __shared__ int s_off;
    int t = threadIdx.x, b = blockIdx.x;
    int gid = b * 1024 + t;
    const int NT = CSR_BLOCKS * 1024;

    // phase A: in-degree histogram (g_cnt zeroed by k_gemm1)
    for (int e = gid; e < EE; e += NT)
        atomicAdd(&g_cnt[dst[e]], 1);
    sw_barrier();

    // phase B: exclusive scan of (deg+1) across all nodes, plus dinv
    int v = (gid < NN) ? (g_cnt[gid] + 1) : 0;   // +1 self loop
    if (gid < NN) g_dinv[gid] = rsqrtf((float)v);
    sh[t] = v;
    __syncthreads();
    for (int off = 1; off < 1024; off <<= 1) {
        int add = (t >= off) ? sh[t - off] : 0;
        __syncthreads();
        sh[t] += add;
        __syncthreads();
    }
    int incl = sh[t];
    if (t == 1023) *(volatile int*)&g_agg[b] = sh[1023];   // block total (>0 always)
    if (t < 32) {
        int sum = 0;
        for (int p = t; p < b; p += 32) {
            int a;
            do { a = *(volatile int*)&g_agg[p]; } while (a == 0);
            sum += a;
        }
#pragma unroll
        for (int off = 16; off > 0; off >>= 1)
            sum += __shfl_xor_sync(0xFFFFFFFFu, sum, off);
        if (t == 0) s_off = sum;
    }
    __syncthreads();
    int rp = s_off + incl - v;
    if (gid < NN) { g_rowptr[gid] = rp; g_pos[gid] = rp; }
    if (gid == 0) g_rowptr[NN] = TOTE;
    sw_barrier();

    // phase C: counting-sort fill (src-only records)
    for (int e = gid; e < TOTE; e += NT) {
        int s, d;
        if (e < EE) { s = src[e]; d = dst[e]; }
        else        { s = d = e - EE; }
        int p = atomicAdd(&g_pos[d], 1);
        g_esrc[p] = s;
    }
}

// ---------------- GEMM1: h0 = relu(x@W1+b1) (half); also zeroes CSR state ----------------
__global__ void __launch_bounds__(256) k_gemm1(const float* __restrict__ x,
                                               const float* __restrict__ W1,
                                               const float* __restrict__ b1) {
    // zero CSR-build state (runs before k_csr in stream order)
    {
        int tg = blockIdx.x * 256 + threadIdx.x;
        if (tg < NN) g_cnt[tg] = 0;
        if (tg < CSR_BLOCKS) g_agg[tg] = 0;
        if (tg == 0) { g_barcnt = 0; g_bargen = 0; }
    }
    __shared__ float Ws[FIN * FHID];
    __shared__ float bs[FHID];
    int tid = threadIdx.x;
    for (int i = tid; i < FIN * FHID / 4; i += 256)
        ((float4*)Ws)[i] = ((const float4*)W1)[i];
    if (tid < FHID) bs[tid] = b1[tid];
    __syncthreads();

    int cg = tid & 7;          // owns cols [cg*8, cg*8+8)
    int rsub = tid >> 3;       // 0..31
    int rowBase = blockIdx.x * 128;

    float acc[4][8];
#pragma unroll
    for (int i = 0; i < 4; i++)
#pragma unroll
        for (int j = 0; j < 8; j++) acc[i][j] = 0.f;

    for (int k4 = 0; k4 < FIN / 4; k4++) {
        float4 xv[4];
#pragma unroll
        for (int i = 0; i < 4; i++) {
            int rr = rowBase + rsub + 32 * i;
            xv[i] = (rr < NN) ? __ldg((const float4*)(x + (size_t)rr * FIN) + k4)
                              : make_float4(0.f, 0.f, 0.f, 0.f);
        }
#pragma unroll
        for (int kk = 0; kk < 4; kk++) {
            int k = k4 * 4 + kk;
            float4 w0 = *(const float4*)&Ws[k * FHID + cg * 8];
            float4 w1 = *(const float4*)&Ws[k * FHID + cg * 8 + 4];
            float wv[8] = {w0.x, w0.y, w0.z, w0.w, w1.x, w1.y, w1.z, w1.w};
#pragma unroll
            for (int i = 0; i < 4; i++) {
                float xs = (kk == 0) ? xv[i].x : (kk == 1) ? xv[i].y
                          : (kk == 2) ? xv[i].z : xv[i].w;
#pragma unroll
                for (int j = 0; j < 8; j++) acc[i][j] += xs * wv[j];
            }
        }
    }
#pragma unroll
    for (int i = 0; i < 4; i++) {
        int rr = rowBase + rsub + 32 * i;
        if (rr < NN) {
            float r[8];
#pragma unroll
            for (int j = 0; j < 8; j++) r[j] = fmaxf(acc[i][j] + bs[cg * 8 + j], 0.f);
            uint4 oh;
            *(__half2*)&oh.x = __floats2half2_rn(r[0], r[1]);
            *(__half2*)&oh.y = __floats2half2_rn(r[2], r[3]);
            *(__half2*)&oh.z = __floats2half2_rn(r[4], r[5]);
            *(__half2*)&oh.w = __floats2half2_rn(r[6], r[7]);
            g_h0[(size_t)rr * 8 + cg] = oh;
        }
    }
}

// ---------------- GEMM2: h0_40 = relu(x10@W2+b2) (half) ----------------
__global__ void __launch_bounds__(256) k_gemm2(const __half* __restrict__ xin,
                                               const float* __restrict__ W2,
                                               const float* __restrict__ b2,
                                               __half* __restrict__ h0o) {
    __shared__ float Ws[FHID * FOUT];
    __shared__ float bs[FOUT];
    int tid = threadIdx.x;
    for (int i = tid; i < FHID * FOUT; i += 256) Ws[i] = W2[i];
    if (tid < FOUT) bs[tid] = b2[tid];
    __syncthreads();

    int cg = tid & 7;          // cols cg + 8*j, j<5
    int rsub = tid >> 3;
    int rowBase = blockIdx.x * 128;

    float acc[4][5];
#pragma unroll
    for (int i = 0; i < 4; i++)
#pragma unroll
        for (int j = 0; j < 5; j++) acc[i][j] = 0.f;

    for (int k8 = 0; k8 < FHID / 8; k8++) {
        float xf[4][8];
#pragma unroll
        for (int i = 0; i < 4; i++) {
            int rr = rowBase + rsub + 32 * i;
            uint4 v = (rr < NN) ? __ldg((const uint4*)xin + (size_t)rr * 8 + k8)
                                : make_uint4(0u, 0u, 0u, 0u);
            float2 f0 = __half22float2(*(__half2*)&v.x);
            float2 f1 = __half22float2(*(__half2*)&v.y);
            float2 f2 = __half22float2(*(__half2*)&v.z);
            float2 f3 = __half22float2(*(__half2*)&v.w);
            xf[i][0] = f0.x; xf[i][1] = f0.y; xf[i][2] = f1.x; xf[i][3] = f1.y;
            xf[i][4] = f2.x; xf[i][5] = f2.y; xf[i][6] = f3.x; xf[i][7] = f3.y;
        }
#pragma unroll
        for (int kk = 0; kk < 8; kk++) {
            int k = k8 * 8 + kk;
            float wv[5];
#pragma unroll
            for (int j = 0; j < 5; j++) wv[j] = Ws[k * FOUT + cg + 8 * j];
#pragma unroll
            for (int i = 0; i < 4; i++)
#pragma unroll
                for (int j = 0; j < 5; j++) acc[i][j] += xf[i][kk] * wv[j];
        }
    }
#pragma unroll
    for (int i = 0; i < 4; i++) {
        int rr = rowBase + rsub + 32 * i;
        if (rr < NN) {
#pragma unroll
            for (int j = 0; j < 5; j++) {
                int c = cg + 8 * j;
                float v = fmaxf(acc[i][j] + bs[c], 0.f);
                h0o[(size_t)rr * FOUT + c] = __float2half_rn(v);
            }
        }
    }
}

// helpers
__device__ __forceinline__ __half2 u2h(unsigned u) { return *(__half2*)&u; }
__device__ __forceinline__ void accH2(__half2& a0, __half2& a1, uint2 v) {
    a0 = __hadd2(a0, u2h(v.x));
    a1 = __hadd2(a1, u2h(v.y));
}
__device__ __forceinline__ void acc_h4f(float4& a, uint2 v, float w) {
    float2 f0 = __half22float2(u2h(v.x));
    float2 f1 = __half22float2(u2h(v.y));
    a.x = fmaf(w, f0.x, a.x);
    a.y = fmaf(w, f0.y, a.y);
    a.z = fmaf(w, f1.x, a.z);
    a.w = fmaf(w, f1.y, a.w);
}

// ---------------- prop F=64: warp/node, 2 groups x 16 lanes x 4 halves, batch-8 --------
// FIRST: zin holds unscaled h0 -> multiply gathered rows by dinv[s] (fp32 path)
// else: HADD2 accumulation, 4 independent half2 accumulator pairs
// FINAL: store unscaled x (for GEMM2 input) instead of dinv-scaled z
template <bool FIRST, bool FINAL>
__global__ void __launch_bounds__(256) k_prop64(const uint2* __restrict__ zin,
                                                const uint2* __restrict__ h0,
                                                uint2* __restrict__ zout) {
    int gw = (blockIdx.x * blockDim.x + threadIdx.x) >> 5;
    int lane = threadIdx.x & 31;
    if (gw >= NN) return;
    int beg = __ldg(&g_rowptr[gw]);
    int end = __ldg(&g_rowptr[gw + 1]);
    int grp = lane >> 4;       // 0,1 (edge stride 2)
    int sub = lane & 15;       // uint2 (4-half) slot within 64-half row
    float4 a = make_float4(0.f, 0.f, 0.f, 0.f);
    __half2 hz = __floats2half2_rn(0.f, 0.f);
    __half2 aA0 = hz, aA1 = hz, aB0 = hz, aB1 = hz;
    __half2 aC0 = hz, aC1 = hz, aD0 = hz, aD1 = hz;
    int j = beg + grp;
    // batch of 8 edges (16 gathers in flight per warp)
    for (; j + 14 < end; j += 16) {
        int s0 = __ldg(&g_esrc[j]);
        int s1 = __ldg(&g_esrc[j + 2]);
        int s2 = __ldg(&g_esrc[j + 4]);
        int s3 = __ldg(&g_esrc[j + 6]);
        int s4 = __ldg(&g_esrc[j + 8]);
        int s5 = __ldg(&g_esrc[j + 10]);
        int s6 = __ldg(&g_esrc[j + 12]);
        int s7 = __ldg(&g_esrc[j + 14]);
        uint2 v0 = __ldg(zin + (size_t)s0 * 16 + sub);
        uint2 v1 = __ldg(zin + (size_t)s1 * 16 + sub);
        uint2 v2 = __ldg(zin + (size_t)s2 * 16 + sub);
        uint2 v3 = __ldg(zin + (size_t)s3 * 16 + sub);
        uint2 v4 = __ldg(zin + (size_t)s4 * 16 + sub);
        uint2 v5 = __ldg(zin + (size_t)s5 * 16 + sub);
        uint2 v6 = __ldg(zin + (size_t)s6 * 16 + sub);
        uint2 v7 = __ldg(zin + (size_t)s7 * 16 + sub);
        if (FIRST) {
            acc_h4f(a, v0, __ldg(&g_dinv[s0]));
            acc_h4f(a, v1, __ldg(&g_dinv[s1]));
            acc_h4f(a, v2, __ldg(&g_dinv[s2]));
            acc_h4f(a, v3, __ldg(&g_dinv[s3]));
            acc_h4f(a, v4, __ldg(&g_dinv[s4]));
            acc_h4f(a, v5, __ldg(&g_dinv[s5]));
            acc_h4f(a, v6, __ldg(&g_dinv[s6]));
            acc_h4f(a, v7, __ldg(&g_dinv[s7]));
        } else {
            accH2(aA0, aA1, v0);
            accH2(aB0, aB1, v1);
            accH2(aC0, aC1, v2);
            accH2(aD0, aD1, v3);
            accH2(aA0, aA1, v4);
            accH2(aB0, aB1, v5);
            accH2(aC0, aC1, v6);
            accH2(aD0, aD1, v7);
        }
    }
    // batch of 4
    if (j + 6 < end) {
        int s0 = __ldg(&g_esrc[j]);
        int s1 = __ldg(&g_esrc[j + 2]);
        int s2 = __ldg(&g_esrc[j + 4]);
        int s3 = __ldg(&g_esrc[j + 6]);
        uint2 v0 = __ldg(zin + (size_t)s0 * 16 + sub);
        uint2 v1 = __ldg(zin + (size_t)s1 * 16 + sub);
        uint2 v2 = __ldg(zin + (size_t)s2 * 16 + sub);
        uint2 v3 = __ldg(zin + (size_t)s3 * 16 + sub);
        if (FIRST) {
            acc_h4f(a, v0, __ldg(&g_dinv[s0]));
            acc_h4f(a, v1, __ldg(&g_dinv[s1]));
            acc_h4f(a, v2, __ldg(&g_dinv[s2]));
            acc_h4f(a, v3, __ldg(&g_dinv[s3]));
        } else {
            accH2(aA0, aA1, v0);
            accH2(aB0, aB1, v1);
            accH2(aC0, aC1, v2);
            accH2(aD0, aD1, v3);
        }
        j += 8;
    }
    // batch of 2
    if (j + 2 < end) {
        int s0 = __ldg(&g_esrc[j]);
        int s1 = __ldg(&g_esrc[j + 2]);
        uint2 v0 = __ldg(zin + (size_t)s0 * 16 + sub);
        uint2 v1 = __ldg(zin + (size_t)s1 * 16 + sub);
        if (FIRST) {
            acc_h4f(a, v0, __ldg(&g_dinv[s0]));
            acc_h4f(a, v1, __ldg(&g_dinv[s1]));
        } else {
            accH2(aA0, aA1, v0);
            accH2(aB0, aB1, v1);
        }
        j += 4;
    }
    // single
    if (j < end) {
        int s0 = __ldg(&g_esrc[j]);
        uint2 v0 = __ldg(zin + (size_t)s0 * 16 + sub);
        if (FIRST) acc_h4f(a, v0, __ldg(&g_dinv[s0]));
        else       accH2(aA0, aA1, v0);
    }
    if (!FIRST) {
        __half2 s0h = __hadd2(__hadd2(aA0, aB0), __hadd2(aC0, aD0));
        __half2 s1h = __hadd2(__hadd2(aA1, aB1), __hadd2(aC1, aD1));
        float2 f0 = __half22float2(s0h);
        float2 f1 = __half22float2(s1h);
        a.x = f0.x; a.y = f0.y; a.z = f1.x; a.w = f1.y;
    }
    a.x += __shfl_down_sync(0xFFFFFFFFu, a.x, 16);
    a.y += __shfl_down_sync(0xFFFFFFFFu, a.y, 16);
    a.z += __shfl_down_sync(0xFFFFFFFFu, a.z, 16);
    a.w += __shfl_down_sync(0xFFFFFFFFu, a.w, 16);
    if (grp == 0) {
        float dv = __ldg(&g_dinv[gw]);
        uint2 hv = __ldg(h0 + (size_t)gw * 16 + sub);
        float2 h0a = __half22float2(u2h(hv.x));
        float2 h0b = __half22float2(u2h(hv.y));
        float c = (1.0f - ALPHA) * dv;
        float x0 = c * a.x + ALPHA * h0a.x;
        float x1 = c * a.y + ALPHA * h0a.y;
        float x2 = c * a.z + ALPHA * h0b.x;
        float x3 = c * a.w + ALPHA * h0b.y;
        float sc = FINAL ? 1.0f : dv;
        uint2 o;
        *(__half2*)&o.x = __floats2half2_rn(sc * x0, sc * x1);
        *(__half2*)&o.y = __floats2half2_rn(sc * x2, sc * x3);
        zout[(size_t)gw * 16 + sub] = o;
    }
}

// ---------------- prop F=40: warp/node, 3 groups x 10 lanes x 4 halves (R9 layout) ------
template <bool FIRST>
__device__ __forceinline__ float4 prop40_acc(int gw, int lane, int grp, int sub,
                                             const uint2* __restrict__ zin) {
    int beg = __ldg(&g_rowptr[gw]);
    int end = __ldg(&g_rowptr[gw + 1]);
    float4 a = make_float4(0.f, 0.f, 0.f, 0.f);
    __half2 hz = __floats2half2_rn(0.f, 0.f);
    __half2 aA0 = hz, aA1 = hz, aB0 = hz, aB1 = hz;
    if (grp < 3) {
        int j = beg + grp;
        for (; j + 9 < end; j += 12) {
            int s0 = __ldg(&g_esrc[j]);
            int s1 = __ldg(&g_esrc[j + 3]);
            int s2 = __ldg(&g_esrc[j + 6]);
            int s3 = __ldg(&g_esrc[j + 9]);
            uint2 v0 = __ldg(zin + (size_t)s0 * 10 + sub);
            uint2 v1 = __ldg(zin + (size_t)s1 * 10 + sub);
            uint2 v2 = __ldg(zin + (size_t)s2 * 10 + sub);
            uint2 v3 = __ldg(zin + (size_t)s3 * 10 + sub);
            if (FIRST) {
                acc_h4f(a, v0, __ldg(&g_dinv[s0]));
                acc_h4f(a, v1, __ldg(&g_dinv[s1]));
                acc_h4f(a, v2, __ldg(&g_dinv[s2]));
                acc_h4f(a, v3, __ldg(&g_dinv[s3]));
            } else {
                accH2(aA0, aA1, v0);
                accH2(aB0, aB1, v1);
                accH2(aA0, aA1, v2);
                accH2(aB0, aB1, v3);
            }
        }
        if (j + 3 < end) {
            int s0 = __ldg(&g_esrc[j]);
            int s1 = __ldg(&g_esrc[j + 3]);
            uint2 v0 = __ldg(zin + (size_t)s0 * 10 + sub);
            uint2 v1 = __ldg(zin + (size_t)s1 * 10 + sub);
            if (FIRST) {
                acc_h4f(a, v0, __ldg(&g_dinv[s0]));
                acc_h4f(a, v1, __ldg(&g_dinv[s1]));
            } else {
                accH2(aA0, aA1, v0);
                accH2(aB0, aB1, v1);
            }
            j += 6;
        }
        if (j < end) {
            int s0 = __ldg(&g_esrc[j]);
            uint2 v0 = __ldg(zin + (size_t)s0 * 10 + sub);
            if (FIRST) acc_h4f(a, v0, __ldg(&g_dinv[s0]));
            else       accH2(aA0, aA1, v0);
        }
        if (!FIRST) {
            float2 fA0 = __half22float2(aA0), fB0 = __half22float2(aB0);
            float2 fA1 = __half22float2(aA1), fB1 = __half22float2(aB1);
            a.x = fA0.x + fB0.x; a.y = fA0.y + fB0.y;
            a.z = fA1.x + fB1.x; a.w = fA1.y + fB1.y;
        }
    }
    int l1 = lane + 10 < 32 ? lane + 10 : lane;
    int l2 = lane + 20 < 32 ? lane + 20 : lane;
    float t1x = __shfl_sync(0xFFFFFFFFu, a.x, l1);
    float t1y = __shfl_sync(0xFFFFFFFFu, a.y, l1);
    float t1z = __shfl_sync(0xFFFFFFFFu, a.z, l1);
    float t1w = __shfl_sync(0xFFFFFFFFu, a.w, l1);
    float t2x = __shfl_sync(0xFFFFFFFFu, a.x, l2);
    float t2y = __shfl_sync(0xFFFFFFFFu, a.y, l2);
    float t2z = __shfl_sync(0xFFFFFFFFu, a.z, l2);
    float t2w = __shfl_sync(0xFFFFFFFFu, a.w, l2);
    a.x += t1x + t2x; a.y += t1y + t2y; a.z += t1z + t2z; a.w += t1w + t2w;
    return a;
}

template <bool FIRST>
__global__ void __launch_bounds__(256) k_prop40(const uint2* __restrict__ zin,
                                                const uint2* __restrict__ h0,
                                                uint2* __restrict__ zout) {
    int gw = (blockIdx.x * blockDim.x + threadIdx.x) >> 5;
    int lane = threadIdx.x & 31;
    if (gw >= NN) return;
    int grp = lane / 10;
    int sub = lane - grp * 10;
    float4 a = prop40_acc<FIRST>(gw, lane, grp, sub, zin);
    if (grp == 0) {
        float dv = __ldg(&g_dinv[gw]);
        uint2 hv = __ldg(h0 + (size_t)gw * 10 + sub);
        float2 h0a = __half22float2(u2h(hv.x));
        float2 h0b = __half22float2(u2h(hv.y));
        float c = (1.0f - ALPHA) * dv;
        float x0 = dv * (c * a.x + ALPHA * h0a.x);
        float x1 = dv * (c * a.y + ALPHA * h0a.y);
        float x2 = dv * (c * a.z + ALPHA * h0b.x);
        float x3 = dv * (c * a.w + ALPHA * h0b.y);
        uint2 o;
        *(__half2*)&o.x = __floats2half2_rn(x0, x1);
        *(__half2*)&o.y = __floats2half2_rn(x2, x3);
        zout[(size_t)gw * 10 + sub] = o;
    }
}

// final F=40 step fused with log_softmax, fp32 output
__global__ void __launch_bounds__(256) k_prop40_lsm(const uint2* __restrict__ zin,
                                                    const uint2* __restrict__ h0,
                                                    float* __restrict__ out) {
    int gw = (blockIdx.x * blockDim.x + threadIdx.x) >> 5;
    int lane = threadIdx.x & 31;
    if (gw >= NN) return;
    int grp = lane / 10;
    int sub = lane - grp * 10;
    float4 a = prop40_acc<false>(gw, lane, grp, sub, zin);
    float dv = __ldg(&g_dinv[gw]);
    float4 v = make_float4(-INFINITY, -INFINITY, -INFINITY, -INFINITY);
    bool act = (grp == 0);
    if (act) {
        uint2 hv = __ldg(h0 + (size_t)gw * 10 + sub);
        float2 h0a = __half22float2(u2h(hv.x));
        float2 h0b = __half22float2(u2h(hv.y));
        float c = (1.0f - ALPHA) * dv;
        v.x = c * a.x + ALPHA * h0a.x;
        v.y = c * a.y + ALPHA * h0a.y;
        v.z = c * a.z + ALPHA * h0b.x;
        v.w = c * a.w + ALPHA * h0b.y;
    }
    float m = act ? fmaxf(fmaxf(v.x, v.y), fmaxf(v.z, v.w)) : -INFINITY;
#pragma unroll
    for (int off = 16; off > 0; off >>= 1)
        m = fmaxf(m, __shfl_xor_sync(0xFFFFFFFFu, m, off));
    float s = act ? (expf(v.x - m) + expf(v.y - m) + expf(v.z - m) + expf(v.w - m)) : 0.f;
#pragma unroll
    for (int off = 16; off > 0; off >>= 1)
        s += __shfl_xor_sync(0xFFFFFFFFu, s, off);
    float lg = m + logf(s);
    if (act) {
        float4 o = make_float4(v.x - lg, v.y - lg, v.z - lg, v.w - lg);
        ((float4*)(out + (size_t)gw * FOUT))[sub] = o;
    }
}

// ---------------- launch ----------------
extern "C" void kernel_launch(void* const* d_in, const int* in_sizes, int n_in,
                              void* d_out, int out_size) {
    const float* x    = (const float*)d_in[0];
    const int*   edge = (const int*)d_in[1];
    const float* W1   = (const float*)d_in[2];
    const float* b1   = (const float*)d_in[3];
    const float* W2   = (const float*)d_in[4];
    const float* b2   = (const float*)d_in[5];
    const int* src = edge;
    const int* dst = edge + EE;

    uint2 *h0, *A, *B;
    cudaGetSymbolAddress((void**)&h0, g_h0);
    cudaGetSymbolAddress((void**)&A, g_bufA);
    cudaGetSymbolAddress((void**)&B, g_bufB);

    const int PROP_BLOCKS = (NN * 32 + 255) / 256;

    // 1: GEMM1 (graph-independent) + zero CSR state
    k_gemm1<<<(NN + 127) / 128, 256>>>(x, W1, b1);
    // 2: fused CSR build
    k_csr<<<CSR_BLOCKS, 1024>>>(src, dst);

    // layer 1 propagation (10 steps); #3 = FIRST, #4 = steady (profiled)
    k_prop64<true, false><<<PROP_BLOCKS, 256>>>(h0, h0, A);
    const uint2* cur = A;
    uint2* nxt = B;
    for (int it = 0; it < KSTEPS - 2; it++) {
        k_prop64<false, false><<<PROP_BLOCKS, 256>>>(cur, h0, nxt);
        const uint2* t = nxt; nxt = (uint2*)cur; cur = t;
    }
    k_prop64<false, true><<<PROP_BLOCKS, 256>>>(cur, h0, nxt);   // unscaled x10

    // layer 2
    uint2* x10 = nxt;
    uint2* other = (x10 == A) ? B : A;
    k_gemm2<<<(NN + 127) / 128, 256>>>((const __half*)x10, W2, b2, (__half*)h0);
    k_prop40<true><<<PROP_BLOCKS, 256>>>(h0, h0, other);
    cur = other;
    nxt = x10;
    for (int it = 0; it < KSTEPS - 2; it++) {
        k_prop40<false><<<PROP_BLOCKS, 256>>>(cur, h0, nxt);
        const uint2* t = nxt; nxt = (uint2*)cur; cur = t;
    }
    k_prop40_lsm<<<PROP_BLOCKS, 256>>>(cur, h0, (float*)d_out);
}

// round 14
// speedup vs baseline: 1.2731x; 1.1431x over previous
#include <cuda_runtime.h>
#include <cuda_fp16.h>
#include <math.h>

#define NN   100000
#define EE   1600000
#define TOTE 1700000   // E + N self loops
#define FIN  128
#define FHID 64
#define FOUT 40
#define KSTEPS 10
#define ALPHA 0.1f
#define CSR_BLOCKS 98

// ---------------- scratch (static device globals; no allocation) ----------------
__device__ int   g_cnt[NN];
__device__ int   g_rowptr[NN + 1];
__device__ int   g_pos[NN];
__device__ float g_dinv[NN];
__device__ int   g_esrc[TOTE];           // src index only (weights folded into iterate)
__device__ int   g_agg[CSR_BLOCKS];      // scan block aggregates (0 = not ready)
__device__ int   g_barcnt;
__device__ int   g_bargen;
// half-precision node-feature buffers, 128B per row (max F=64 halves)
__device__ uint4 g_h0[NN * 8];           // teleport target
__device__ uint4 g_bufA[NN * 8];
__device__ uint4 g_bufB[NN * 8];

// ---------------- software grid barrier (all CSR_BLOCKS resident) ----------------
__device__ __forceinline__ void sw_barrier() {
    __syncthreads();
    if (threadIdx.x == 0) {
        __threadfence();
        int gen = *(volatile int*)&g_bargen;
        int t = atomicAdd(&g_barcnt, 1);
        if (t == CSR_BLOCKS - 1) {
            g_barcnt = 0;
            __threadfence();
            *(volatile int*)&g_bargen = gen + 1;
        } else {
            while (*(volatile int*)&g_bargen == gen) {}
        }
        __threadfence();
    }
    __syncthreads();
}

// ---------------- fused CSR build: degree -> scan -> fill ----------------
__global__ void __launch_bounds__(1024) k_csr(const int* __restrict__ src,
                                              const int* __restrict__ dst) {
    __shared__ int sh[1024];
    __shared__ int s_off;
    int t = threadIdx.x, b = blockIdx.x;
    int gid = b * 1024 + t;
    const int NT = CSR_BLOCKS * 1024;

    // phase A: in-degree histogram (g_cnt zeroed by k_gemm1)
    for (int e = gid; e < EE; e += NT)
        atomicAdd(&g_cnt[dst[e]], 1);
    sw_barrier();

    // phase B: exclusive scan of (deg+1) across all nodes, plus dinv
    int v = (gid < NN) ? (g_cnt[gid] + 1) : 0;   // +1 self loop
    if (gid < NN) g_dinv[gid] = rsqrtf((float)v);
    sh[t] = v;
    __syncthreads();
    for (int off = 1; off < 1024; off <<= 1) {
        int add = (t >= off) ? sh[t - off] : 0;
        __syncthreads();
        sh[t] += add;
        __syncthreads();
    }
    int incl = sh[t];
    if (t == 1023) *(volatile int*)&g_agg[b] = sh[1023];   // block total (>0 always)
    if (t < 32) {
        int sum = 0;
        for (int p = t; p < b; p += 32) {
            int a;
            do { a = *(volatile int*)&g_agg[p]; } while (a == 0);
            sum += a;
        }
#pragma unroll
        for (int off = 16; off > 0; off >>= 1)
            sum += __shfl_xor_sync(0xFFFFFFFFu, sum, off);
        if (t == 0) s_off = sum;
    }
    __syncthreads();
    int rp = s_off + incl - v;
    if (gid < NN) { g_rowptr[gid] = rp; g_pos[gid] = rp; }
    if (gid == 0) g_rowptr[NN] = TOTE;
    sw_barrier();

    // phase C: counting-sort fill (src-only records)
    for (int e = gid; e < TOTE; e += NT) {
        int s, d;
        if (e < EE) { s = src[e]; d = dst[e]; }
        else        { s = d = e - EE; }
        int p = atomicAdd(&g_pos[d], 1);
        g_esrc[p] = s;
    }
}

// ---------------- GEMM1: h0 = relu(x@W1+b1) (half); also zeroes CSR state ----------------
__global__ void __launch_bounds__(256) k_gemm1(const float* __restrict__ x,
                                               const float* __restrict__ W1,
                                               const float* __restrict__ b1) {
    // zero CSR-build state (runs before k_csr in stream order)
    {
        int tg = blockIdx.x * 256 + threadIdx.x;
        if (tg < NN) g_cnt[tg] = 0;
        if (tg < CSR_BLOCKS) g_agg[tg] = 0;
        if (tg == 0) { g_barcnt = 0; g_bargen = 0; }
    }
    __shared__ float Ws[FIN * FHID];
    __shared__ float bs[FHID];
    int tid = threadIdx.x;
    for (int i = tid; i < FIN * FHID / 4; i += 256)
        ((float4*)Ws)[i] = ((const float4*)W1)[i];
    if (tid < FHID) bs[tid] = b1[tid];
    __syncthreads();

    int cg = tid & 7;          // owns cols [cg*8, cg*8+8)
    int rsub = tid >> 3;       // 0..31
    int rowBase = blockIdx.x * 128;

    float acc[4][8];
#pragma unroll
    for (int i = 0; i < 4; i++)
#pragma unroll
        for (int j = 0; j < 8; j++) acc[i][j] = 0.f;

    for (int k4 = 0; k4 < FIN / 4; k4++) {
        float4 xv[4];
#pragma unroll
        for (int i = 0; i < 4; i++) {
            int rr = rowBase + rsub + 32 * i;
            xv[i] = (rr < NN) ? __ldg((const float4*)(x + (size_t)rr * FIN) + k4)
                              : make_float4(0.f, 0.f, 0.f, 0.f);
        }
#pragma unroll
        for (int kk = 0; kk < 4; kk++) {
            int k = k4 * 4 + kk;
            float4 w0 = *(const float4*)&Ws[k * FHID + cg * 8];
            float4 w1 = *(const float4*)&Ws[k * FHID + cg * 8 + 4];
            float wv[8] = {w0.x, w0.y, w0.z, w0.w, w1.x, w1.y, w1.z, w1.w};
#pragma unroll
            for (int i = 0; i < 4; i++) {
                float xs = (kk == 0) ? xv[i].x : (kk == 1) ? xv[i].y
                          : (kk == 2) ? xv[i].z : xv[i].w;
#pragma unroll
                for (int j = 0; j < 8; j++) acc[i][j] += xs * wv[j];
            }
        }
    }
#pragma unroll
    for (int i = 0; i < 4; i++) {
        int rr = rowBase + rsub + 32 * i;
        if (rr < NN) {
            float r[8];
#pragma unroll
            for (int j = 0; j < 8; j++) r[j] = fmaxf(acc[i][j] + bs[cg * 8 + j], 0.f);
            uint4 oh;
            *(__half2*)&oh.x = __floats2half2_rn(r[0], r[1]);
            *(__half2*)&oh.y = __floats2half2_rn(r[2], r[3]);
            *(__half2*)&oh.z = __floats2half2_rn(r[4], r[5]);
            *(__half2*)&oh.w = __floats2half2_rn(r[6], r[7]);
            g_h0[(size_t)rr * 8 + cg] = oh;
        }
    }
}

// ---------------- GEMM2: h0_40 = relu(x10@W2+b2) (half) ----------------
__global__ void __launch_bounds__(256) k_gemm2(const __half* __restrict__ xin,
                                               const float* __restrict__ W2,
                                               const float* __restrict__ b2,
                                               __half* __restrict__ h0o) {
    __shared__ float Ws[FHID * FOUT];
    __shared__ float bs[FOUT];
    int tid = threadIdx.x;
    for (int i = tid; i < FHID * FOUT; i += 256) Ws[i] = W2[i];
    if (tid < FOUT) bs[tid] = b2[tid];
    __syncthreads();

    int cg = tid & 7;          // cols cg + 8*j, j<5
    int rsub = tid >> 3;
    int rowBase = blockIdx.x * 128;

    float acc[4][5];
#pragma unroll
    for (int i = 0; i < 4; i++)
#pragma unroll
        for (int j = 0; j < 5; j++) acc[i][j] = 0.f;

    for (int k8 = 0; k8 < FHID / 8; k8++) {
        float xf[4][8];
#pragma unroll
        for (int i = 0; i < 4; i++) {
            int rr = rowBase + rsub + 32 * i;
            uint4 v = (rr < NN) ? __ldg((const uint4*)xin + (size_t)rr * 8 + k8)
                                : make_uint4(0u, 0u, 0u, 0u);
            float2 f0 = __half22float2(*(__half2*)&v.x);
            float2 f1 = __half22float2(*(__half2*)&v.y);
            float2 f2 = __half22float2(*(__half2*)&v.z);
            float2 f3 = __half22float2(*(__half2*)&v.w);
            xf[i][0] = f0.x; xf[i][1] = f0.y; xf[i][2] = f1.x; xf[i][3] = f1.y;
            xf[i][4] = f2.x; xf[i][5] = f2.y; xf[i][6] = f3.x; xf[i][7] = f3.y;
        }
#pragma unroll
        for (int kk = 0; kk < 8; kk++) {
            int k = k8 * 8 + kk;
            float wv[5];
#pragma unroll
            for (int j = 0; j < 5; j++) wv[j] = Ws[k * FOUT + cg + 8 * j];
#pragma unroll
            for (int i = 0; i < 4; i++)
#pragma unroll
                for (int j = 0; j < 5; j++) acc[i][j] += xf[i][kk] * wv[j];
        }
    }
#pragma unroll
    for (int i = 0; i < 4; i++) {
        int rr = rowBase + rsub + 32 * i;
        if (rr < NN) {
#pragma unroll
            for (int j = 0; j < 5; j++) {
                int c = cg + 8 * j;
                float v = fmaxf(acc[i][j] + bs[c], 0.f);
                h0o[(size_t)rr * FOUT + c] = __float2half_rn(v);
            }
        }
    }
}

// helpers
__device__ __forceinline__ __half2 u2h(unsigned u) { return *(__half2*)&u; }
__device__ __forceinline__ void accH2(__half2& a0, __half2& a1, uint2 v) {
    a0 = __hadd2(a0, u2h(v.x));
    a1 = __hadd2(a1, u2h(v.y));
}
__device__ __forceinline__ void acc_h4f(float4& a, uint2 v, float w) {
    float2 f0 = __half22float2(u2h(v.x));
    float2 f1 = __half22float2(u2h(v.y));
    a.x = fmaf(w, f0.x, a.x);
    a.y = fmaf(w, f0.y, a.y);
    a.z = fmaf(w, f1.x, a.z);
    a.w = fmaf(w, f1.y, a.w);
}

// ---------------- prop F=64: warp/node, 2 groups x 16 lanes x 4 halves, batch-4 --------
// (R9 structure — validated optimum for MLP/occupancy tradeoff)
template <bool FIRST, bool FINAL>
__global__ void __launch_bounds__(128) k_prop64(const uint2* __restrict__ zin,
                                                const uint2* __restrict__ h0,
                                                uint2* __restrict__ zout) {
    int gw = (blockIdx.x * blockDim.x + threadIdx.x) >> 5;
    int lane = threadIdx.x & 31;
    if (gw >= NN) return;
    int beg = __ldg(&g_rowptr[gw]);
    int end = __ldg(&g_rowptr[gw + 1]);
    int grp = lane >> 4;       // 0,1 (edge stride 2)
    int sub = lane & 15;       // uint2 (4-half) slot within 64-half row
    // hoist epilogue loads so their latency overlaps the edge loop
    float dv = 0.f;
    uint2 hv = make_uint2(0u, 0u);
    if (grp == 0) {
        dv = __ldg(&g_dinv[gw]);
        hv = __ldg(h0 + (size_t)gw * 16 + sub);
    }
    float4 a = make_float4(0.f, 0.f, 0.f, 0.f);
    __half2 hz = __floats2half2_rn(0.f, 0.f);
    __half2 aA0 = hz, aA1 = hz, aB0 = hz, aB1 = hz;
    int j = beg + grp;
    for (; j + 6 < end; j += 8) {
        int s0 = __ldg(&g_esrc[j]);
        int s1 = __ldg(&g_esrc[j + 2]);
        int s2 = __ldg(&g_esrc[j + 4]);
        int s3 = __ldg(&g_esrc[j + 6]);
        uint2 v0 = __ldg(zin + (size_t)s0 * 16 + sub);
        uint2 v1 = __ldg(zin + (size_t)s1 * 16 + sub);
        uint2 v2 = __ldg(zin + (size_t)s2 * 16 + sub);
        uint2 v3 = __ldg(zin + (size_t)s3 * 16 + sub);
        if (FIRST) {
            acc_h4f(a, v0, __ldg(&g_dinv[s0]));
            acc_h4f(a, v1, __ldg(&g_dinv[s1]));
            acc_h4f(a, v2, __ldg(&g_dinv[s2]));
            acc_h4f(a, v3, __ldg(&g_dinv[s3]));
        } else {
            accH2(aA0, aA1, v0);
            accH2(aB0, aB1, v1);
            accH2(aA0, aA1, v2);
            accH2(aB0, aB1, v3);
        }
    }
    if (j + 2 < end) {
        int s0 = __ldg(&g_esrc[j]);
        int s1 = __ldg(&g_esrc[j + 2]);
        uint2 v0 = __ldg(zin + (size_t)s0 * 16 + sub);
        uint2 v1 = __ldg(zin + (size_t)s1 * 16 + sub);
        if (FIRST) {
            acc_h4f(a, v0, __ldg(&g_dinv[s0]));
            acc_h4f(a, v1, __ldg(&g_dinv[s1]));
        } else {
            accH2(aA0, aA1, v0);
            accH2(aB0, aB1, v1);
        }
        j += 4;
    }
    if (j < end) {
        int s0 = __ldg(&g_esrc[j]);
        uint2 v0 = __ldg(zin + (size_t)s0 * 16 + sub);
        if (FIRST) acc_h4f(a, v0, __ldg(&g_dinv[s0]));
        else       accH2(aA0, aA1, v0);
    }
    if (!FIRST) {
        float2 fA0 = __half22float2(aA0), fB0 = __half22float2(aB0);
        float2 fA1 = __half22float2(aA1), fB1 = __half22float2(aB1);
        a.x = fA0.x + fB0.x; a.y = fA0.y + fB0.y;
        a.z = fA1.x + fB1.x; a.w = fA1.y + fB1.y;
    }
    a.x += __shfl_down_sync(0xFFFFFFFFu, a.x, 16);
    a.y += __shfl_down_sync(0xFFFFFFFFu, a.y, 16);
    a.z += __shfl_down_sync(0xFFFFFFFFu, a.z, 16);
    a.w += __shfl_down_sync(0xFFFFFFFFu, a.w, 16);
    if (grp == 0) {
        float2 h0a = __half22float2(u2h(hv.x));
        float2 h0b = __half22float2(u2h(hv.y));
        float c = (1.0f - ALPHA) * dv;
        float x0 = c * a.x + ALPHA * h0a.x;
        float x1 = c * a.y + ALPHA * h0a.y;
        float x2 = c * a.z + ALPHA * h0b.x;
        float x3 = c * a.w + ALPHA * h0b.y;
        float sc = FINAL ? 1.0f : dv;
        uint2 o;
        *(__half2*)&o.x = __floats2half2_rn(sc * x0, sc * x1);
        *(__half2*)&o.y = __floats2half2_rn(sc * x2, sc * x3);
        zout[(size_t)gw * 16 + sub] = o;
    }
}

// ---------------- prop F=40: warp/node, 3 groups x 10 lanes x 4 halves (R9 layout) ------
template <bool FIRST>
__device__ __forceinline__ float4 prop40_acc(int gw, int lane, int grp, int sub,
                                             const uint2* __restrict__ zin) {
    int beg = __ldg(&g_rowptr[gw]);
    int end = __ldg(&g_rowptr[gw + 1]);
    float4 a = make_float4(0.f, 0.f, 0.f, 0.f);
    __half2 hz = __floats2half2_rn(0.f, 0.f);
    __half2 aA0 = hz, aA1 = hz, aB0 = hz, aB1 = hz;
    if (grp < 3) {
        int j = beg + grp;
        for (; j + 9 < end; j += 12) {
            int s0 = __ldg(&g_esrc[j]);
            int s1 = __ldg(&g_esrc[j + 3]);
            int s2 = __ldg(&g_esrc[j + 6]);
            int s3 = __ldg(&g_esrc[j + 9]);
            uint2 v0 = __ldg(zin + (size_t)s0 * 10 + sub);
            uint2 v1 = __ldg(zin + (size_t)s1 * 10 + sub);
            uint2 v2 = __ldg(zin + (size_t)s2 * 10 + sub);
            uint2 v3 = __ldg(zin + (size_t)s3 * 10 + sub);
            if (FIRST) {
                acc_h4f(a, v0, __ldg(&g_dinv[s0]));
                acc_h4f(a, v1, __ldg(&g_dinv[s1]));
                acc_h4f(a, v2, __ldg(&g_dinv[s2]));
                acc_h4f(a, v3, __ldg(&g_dinv[s3]));
            } else {
                accH2(aA0, aA1, v0);
                accH2(aB0, aB1, v1);
                accH2(aA0, aA1, v2);
                accH2(aB0, aB1, v3);
            }
        }
        if (j + 3 < end) {
            int s0 = __ldg(&g_esrc[j]);
            int s1 = __ldg(&g_esrc[j + 3]);
            uint2 v0 = __ldg(zin + (size_t)s0 * 10 + sub);
            uint2 v1 = __ldg(zin + (size_t)s1 * 10 + sub);
            if (FIRST) {
                acc_h4f(a, v0, __ldg(&g_dinv[s0]));
                acc_h4f(a, v1, __ldg(&g_dinv[s1]));
            } else {
                accH2(aA0, aA1, v0);
                accH2(aB0, aB1, v1);
            }
            j += 6;
        }
        if (j < end) {
            int s0 = __ldg(&g_esrc[j]);
            uint2 v0 = __ldg(zin + (size_t)s0 * 10 + sub);
            if (FIRST) acc_h4f(a, v0, __ldg(&g_dinv[s0]));
            else       accH2(aA0, aA1, v0);
        }
        if (!FIRST) {
            float2 fA0 = __half22float2(aA0), fB0 = __half22float2(aB0);
            float2 fA1 = __half22float2(aA1), fB1 = __half22float2(aB1);
            a.x = fA0.x + fB0.x; a.y = fA0.y + fB0.y;
            a.z = fA1.x + fB1.x; a.w = fA1.y + fB1.y;
        }
    }
    int l1 = lane + 10 < 32 ? lane + 10 : lane;
    int l2 = lane + 20 < 32 ? lane + 20 : lane;
    float t1x = __shfl_sync(0xFFFFFFFFu, a.x, l1);
    float t1y = __shfl_sync(0xFFFFFFFFu, a.y, l1);
    float t1z = __shfl_sync(0xFFFFFFFFu, a.z, l1);
    float t1w = __shfl_sync(0xFFFFFFFFu, a.w, l1);
    float t2x = __shfl_sync(0xFFFFFFFFu, a.x, l2);
    float t2y = __shfl_sync(0xFFFFFFFFu, a.y, l2);
    float t2z = __shfl_sync(0xFFFFFFFFu, a.z, l2);
    float t2w = __shfl_sync(0xFFFFFFFFu, a.w, l2);
    a.x += t1x + t2x; a.y += t1y + t2y; a.z += t1z + t2z; a.w += t1w + t2w;
    return a;
}

template <bool FIRST>
__global__ void __launch_bounds__(128) k_prop40(const uint2* __restrict__ zin,
                                                const uint2* __restrict__ h0,
                                                uint2* __restrict__ zout) {
    int gw = (blockIdx.x * blockDim.x + threadIdx.x) >> 5;
    int lane = threadIdx.x & 31;
    if (gw >= NN) return;
    int grp = lane / 10;
    int sub = lane - grp * 10;
    float dv = 0.f;
    uint2 hv = make_uint2(0u, 0u);
    if (grp == 0) {
        dv = __ldg(&g_dinv[gw]);
        hv = __ldg(h0 + (size_t)gw * 10 + sub);
    }
    float4 a = prop40_acc<FIRST>(gw, lane, grp, sub, zin);
    if (grp == 0) {
        float2 h0a = __half22float2(u2h(hv.x));
        float2 h0b = __half22float2(u2h(hv.y));
        float c = (1.0f - ALPHA) * dv;
        float x0 = dv * (c * a.x + ALPHA * h0a.x);
        float x1 = dv * (c * a.y + ALPHA * h0a.y);
        float x2 = dv * (c * a.z + ALPHA * h0b.x);
        float x3 = dv * (c * a.w + ALPHA * h0b.y);
        uint2 o;
        *(__half2*)&o.x = __floats2half2_rn(x0, x1);
        *(__half2*)&o.y = __floats2half2_rn(x2, x3);
        zout[(size_t)gw * 10 + sub] = o;
    }
}

// final F=40 step fused with log_softmax, fp32 output
__global__ void __launch_bounds__(128) k_prop40_lsm(const uint2* __restrict__ zin,
                                                    const uint2* __restrict__ h0,
                                                    float* __restrict__ out) {
    int gw = (blockIdx.x * blockDim.x + threadIdx.x) >> 5;
    int lane = threadIdx.x & 31;
    if (gw >= NN) return;
    int grp = lane / 10;
    int sub = lane - grp * 10;
    float dv = 0.f;
    uint2 hv = make_uint2(0u, 0u);
    bool act = (grp == 0);
    if (act) {
        dv = __ldg(&g_dinv[gw]);
        hv = __ldg(h0 + (size_t)gw * 10 + sub);
    }
    float4 a = prop40_acc<false>(gw, lane, grp, sub, zin);
    float4 v = make_float4(-INFINITY, -INFINITY, -INFINITY, -INFINITY);
    if (act) {
        float2 h0a = __half22float2(u2h(hv.x));
        float2 h0b = __half22float2(u2h(hv.y));
        float c = (1.0f - ALPHA) * dv;
        v.x = c * a.x + ALPHA * h0a.x;
        v.y = c * a.y + ALPHA * h0a.y;
        v.z = c * a.z + ALPHA * h0b.x;
        v.w = c * a.w + ALPHA * h0b.y;
    }
    float m = act ? fmaxf(fmaxf(v.x, v.y), fmaxf(v.z, v.w)) : -INFINITY;
#pragma unroll
    for (int off = 16; off > 0; off >>= 1)
        m = fmaxf(m, __shfl_xor_sync(0xFFFFFFFFu, m, off));
    float s = act ? (expf(v.x - m) + expf(v.y - m) + expf(v.z - m) + expf(v.w - m)) : 0.f;
#pragma unroll
    for (int off = 16; off > 0; off >>= 1)
        s += __shfl_xor_sync(0xFFFFFFFFu, s, off);
    float lg = m + logf(s);
    if (act) {
        float4 o = make_float4(v.x - lg, v.y - lg, v.z - lg, v.w - lg);
        ((float4*)(out + (size_t)gw * FOUT))[sub] = o;
    }
}

// ---------------- launch ----------------
extern "C" void kernel_launch(void* const* d_in, const int* in_sizes, int n_in,
                              void* d_out, int out_size) {
    const float* x    = (const float*)d_in[0];
    const int*   edge = (const int*)d_in[1];
    const float* W1   = (const float*)d_in[2];
    const float* b1   = (const float*)d_in[3];
    const float* W2   = (const float*)d_in[4];
    const float* b2   = (const float*)d_in[5];
    const int* src = edge;
    const int* dst = edge + EE;

    uint2 *h0, *A, *B;
    cudaGetSymbolAddress((void**)&h0, g_h0);
    cudaGetSymbolAddress((void**)&A, g_bufA);
    cudaGetSymbolAddress((void**)&B, g_bufB);

    const int PROP_BLOCKS = (NN * 32 + 127) / 128;   // 128-thread prop CTAs

    // 1: GEMM1 (graph-independent) + zero CSR state
    k_gemm1<<<(NN + 127) / 128, 256>>>(x, W1, b1);
    // 2: fused CSR build
    k_csr<<<CSR_BLOCKS, 1024>>>(src, dst);

    // layer 1 propagation (10 steps); #3 = FIRST, #4 = steady (profiled)
    k_prop64<true, false><<<PROP_BLOCKS, 128>>>(h0, h0, A);
    const uint2* cur = A;
    uint2* nxt = B;
    for (int it = 0; it < KSTEPS - 2; it++) {
        k_prop64<false, false><<<PROP_BLOCKS, 128>>>(cur, h0, nxt);
        const uint2* t = nxt; nxt = (uint2*)cur; cur = t;
    }
    k_prop64<false, true><<<PROP_BLOCKS, 128>>>(cur, h0, nxt);   // unscaled x10

    // layer 2
    uint2* x10 = nxt;
    uint2* other = (x10 == A) ? B : A;
    k_gemm2<<<(NN + 127) / 128, 256>>>((const __half*)x10, W2, b2, (__half*)h0);
    k_prop40<true><<<PROP_BLOCKS, 128>>>(h0, h0, other);
    cur = other;
    nxt = x10;
    for (int it = 0; it < KSTEPS - 2; it++) {
        k_prop40<false><<<PROP_BLOCKS, 128>>>(cur, h0, nxt);
        const uint2* t = nxt; nxt = (uint2*)cur; cur = t;
    }
    k_prop40_lsm<<<PROP_BLOCKS, 128>>>(cur, h0, (float*)d_out);
}